// round 4
// baseline (speedup 1.0000x reference)
#include <cuda_runtime.h>
#include <cuda_bf16.h>
#include <cstdint>

#define NTOK_MAX (8 * 4096)
#define IN_F 1024
#define CUT1 5000
#define CUT2 20000

__device__ int g_cnt[2];
__device__ int g_idx0[NTOK_MAX];
__device__ int g_idx1[NTOK_MAX];

// Dense packed split-bf16 operands.
// A' row: [Ah(K) | Al(K) | Ah(K)]  (K' = 3K)
// B' row: [Bh(K) | Bh(K) | Bl(K)]
__device__ __align__(16) __nv_bfloat16 g_A0[NTOK_MAX * 1536];
__device__ __align__(16) __nv_bfloat16 g_A1[NTOK_MAX * 768];
__device__ __align__(16) __nv_bfloat16 g_B0[1024 * 1536];
__device__ __align__(16) __nv_bfloat16 g_B1[1024 * 768];

// ---------------------------------------------------------------------------
__global__ void init_k() { g_cnt[0] = 0; g_cnt[1] = 0; }

__global__ void classify_k(const int* __restrict__ tokens, int n) {
    int i = blockIdx.x * blockDim.x + threadIdx.x;
    int t = (i < n) ? tokens[i] : -1;
    int c = (t >= CUT2) ? 1 : ((t >= CUT1) ? 0 : -1);
    int lane = threadIdx.x & 31;
#pragma unroll
    for (int cc = 0; cc < 2; ++cc) {
        unsigned m = __ballot_sync(0xffffffffu, c == cc);
        if (c == cc) {
            int leader = __ffs(m) - 1;
            int base = 0;
            if (lane == leader) base = atomicAdd(&g_cnt[cc], __popc(m));
            base = __shfl_sync(m, base, leader);
            int off = base + __popc(m & ((1u << lane) - 1u));
            if (cc == 0) g_idx0[off] = i;
            else         g_idx1[off] = i;
        }
    }
}

__global__ void head_copy_k(const int* __restrict__ tokens,
                            const float* __restrict__ head_emb,
                            float* __restrict__ out) {
    int p = blockIdx.x;
    int t = __ldg(&tokens[p]);
    if (t >= CUT1) return;
    const float4* src = (const float4*)(head_emb + (size_t)t * IN_F);
    float4* dst = (float4*)(out + (size_t)p * IN_F);
    dst[threadIdx.x]       = src[threadIdx.x];
    dst[threadIdx.x + 128] = src[threadIdx.x + 128];
}

// ---------------------------------------------------------------------------
__device__ __forceinline__ void hilo4(float4 v, uint2& hi, uint2& lo) {
    float f[4] = {v.x, v.y, v.z, v.w};
    __nv_bfloat16 h[4], l[4];
#pragma unroll
    for (int i = 0; i < 4; i++) {
        h[i] = __float2bfloat16(f[i]);
        l[i] = __float2bfloat16(f[i] - __bfloat162float(h[i]));
    }
    hi.x = ((uint32_t)*(uint16_t*)&h[1] << 16) | *(uint16_t*)&h[0];
    hi.y = ((uint32_t)*(uint16_t*)&h[3] << 16) | *(uint16_t*)&h[2];
    lo.x = ((uint32_t)*(uint16_t*)&l[1] << 16) | *(uint16_t*)&l[0];
    lo.y = ((uint32_t)*(uint16_t*)&l[3] << 16) | *(uint16_t*)&l[2];
}

// Gather + split-convert embedding rows into dense A'. 16 floats per thread
// (4 independent float4 loads in flight).
template <int K, int LOW, int C>
__global__ void pack_emb_k(const float* __restrict__ emb,
                           const int* __restrict__ tokens,
                           __nv_bfloat16* __restrict__ Ap) {
    constexpr int TPR = K / 16;
    constexpr int RPB = 256 / TPR;
    const int count = g_cnt[C];
    int r = blockIdx.x * RPB + threadIdx.x / TPR;
    if (r >= count) return;
    int j = (threadIdx.x % TPR) * 16;
    const int* idxList = (C == 0) ? g_idx0 : g_idx1;
    int tok = __ldg(&tokens[idxList[r]]);
    const float4* src = (const float4*)(emb + (size_t)(tok - LOW) * K + j);
    float4 v[4];
#pragma unroll
    for (int q = 0; q < 4; q++) v[q] = src[q];
    uint2 hi[4], lo[4];
#pragma unroll
    for (int q = 0; q < 4; q++) hilo4(v[q], hi[q], lo[q]);
    __nv_bfloat16* row = Ap + (size_t)r * (3 * K);
#pragma unroll
    for (int q = 0; q < 2; q++) {
        uint4 H = make_uint4(hi[2*q].x, hi[2*q].y, hi[2*q+1].x, hi[2*q+1].y);
        uint4 L = make_uint4(lo[2*q].x, lo[2*q].y, lo[2*q+1].x, lo[2*q+1].y);
        *(uint4*)(row + j + q * 8)         = H;
        *(uint4*)(row + K + j + q * 8)     = L;
        *(uint4*)(row + 2 * K + j + q * 8) = H;
    }
}

template <int K>
__global__ void pack_w_k(const float* __restrict__ w,
                         __nv_bfloat16* __restrict__ Bp) {
    constexpr int TPR = K / 16;
    constexpr int RPB = 256 / TPR;
    int r = blockIdx.x * RPB + threadIdx.x / TPR;
    int j = (threadIdx.x % TPR) * 16;
    const float4* src = (const float4*)(w + (size_t)r * K + j);
    float4 v[4];
#pragma unroll
    for (int q = 0; q < 4; q++) v[q] = src[q];
    uint2 hi[4], lo[4];
#pragma unroll
    for (int q = 0; q < 4; q++) hilo4(v[q], hi[q], lo[q]);
    __nv_bfloat16* row = Bp + (size_t)r * (3 * K);
#pragma unroll
    for (int q = 0; q < 2; q++) {
        uint4 H = make_uint4(hi[2*q].x, hi[2*q].y, hi[2*q+1].x, hi[2*q+1].y);
        uint4 L = make_uint4(lo[2*q].x, lo[2*q].y, lo[2*q+1].x, lo[2*q+1].y);
        *(uint4*)(row + j + q * 8)         = H;
        *(uint4*)(row + K + j + q * 8)     = H;
        *(uint4*)(row + 2 * K + j + q * 8) = L;
    }
}

// ---------------------------------------------------------------------------
__device__ __forceinline__ void ldsm_x4(uint32_t& r0, uint32_t& r1,
                                        uint32_t& r2, uint32_t& r3,
                                        const void* smem_ptr) {
    uint32_t addr = (uint32_t)__cvta_generic_to_shared(smem_ptr);
    asm volatile("ldmatrix.sync.aligned.m8n8.x4.shared.b16 {%0,%1,%2,%3}, [%4];"
                 : "=r"(r0), "=r"(r1), "=r"(r2), "=r"(r3) : "r"(addr));
}

__device__ __forceinline__ void mma16816(float* c, const uint32_t* a,
                                         uint32_t b0, uint32_t b1) {
    asm volatile(
        "mma.sync.aligned.m16n8k16.row.col.f32.bf16.bf16.f32 "
        "{%0,%1,%2,%3}, {%4,%5,%6,%7}, {%8,%9}, {%0,%1,%2,%3};"
        : "+f"(c[0]), "+f"(c[1]), "+f"(c[2]), "+f"(c[3])
        : "r"(a[0]), "r"(a[1]), "r"(a[2]), "r"(a[3]), "r"(b0), "r"(b1));
}

__device__ __forceinline__ void cp16(void* dst_smem, const void* src) {
    uint32_t d = (uint32_t)__cvta_generic_to_shared(dst_smem);
    asm volatile("cp.async.cg.shared.global [%0], [%1], 16;\n" :: "r"(d), "l"(src));
}

// ---------------------------------------------------------------------------
// Dense bf16 GEMM: out[pos[r], n] = sum_k A'[r,k] B'[n,k]
// Tile 64x128, TK=32, 3-stage cp.async, 8 warps (2M x 4N, warp tile 32x32).
template <int K3, int C>
__global__ void __launch_bounds__(256, 2)
tail_mma2_k(const __nv_bfloat16* __restrict__ Ap,
            const __nv_bfloat16* __restrict__ Bp,
            float* __restrict__ out) {
    constexpr int TM = 64, TN = 128, LD = 40;   // LD halves (32 + 8 pad)
    constexpr int NC = K3 / 32;
    __shared__ __align__(16) __nv_bfloat16 As[3][TM][LD];
    __shared__ __align__(16) __nv_bfloat16 Bs[3][TN][LD];
    __shared__ int sPos[TM];

    const int count = g_cnt[C];
    const int rowBase = blockIdx.x * TM;
    if (rowBase >= count) return;
    const int rem = min(TM, count - rowBase);
    const int n0 = blockIdx.y * TN;
    const int tid = threadIdx.x;
    const int lane = tid & 31;
    const int wid = tid >> 5;
    const int* idxList = (C == 0) ? g_idx0 : g_idx1;

    if (tid < TM) sPos[tid] = idxList[rowBase + min(tid, rem - 1)];

    // loaders: per stage A = 64 rows x 4 segs (1 cp/thread), B = 128 rows (2 cp/thread)
    const int lr = tid >> 2;          // 0..63
    const int seg = (tid & 3) * 8;    // half offset of 16B segment
    const __nv_bfloat16* aP = Ap + (size_t)(rowBase + min(lr, rem - 1)) * K3 + seg;
    const __nv_bfloat16* bP0 = Bp + (size_t)(n0 + lr) * K3 + seg;
    const __nv_bfloat16* bP1 = Bp + (size_t)(n0 + lr + 64) * K3 + seg;

#define ISSUE(s, kc)                                         \
    do {                                                     \
        cp16(&As[s][lr][seg], aP + (kc) * 32);               \
        cp16(&Bs[s][lr][seg], bP0 + (kc) * 32);              \
        cp16(&Bs[s][lr + 64][seg], bP1 + (kc) * 32);         \
    } while (0)

    ISSUE(0, 0);
    asm volatile("cp.async.commit_group;\n");
    ISSUE(1, 1);
    asm volatile("cp.async.commit_group;\n");

    const int wm = (wid & 1) * 32;
    const int wn = (wid >> 1) * 32;
    float c[2][4][4];
#pragma unroll
    for (int i = 0; i < 2; i++)
#pragma unroll
        for (int j = 0; j < 4; j++)
#pragma unroll
            for (int q = 0; q < 4; q++) c[i][j][q] = 0.f;

    const int aLdRow = lane & 15;
    const int aLdCol = (lane >> 4) * 8;
    const int bLdRow = ((lane >> 4) << 3) + (lane & 7);
    const int bLdCol = lane & 8;

    int s = 0;
    for (int kc = 0; kc < NC; kc++) {
        asm volatile("cp.async.wait_group 1;\n");
        __syncthreads();

        int kn = kc + 2;
        if (kn < NC) {
            int sn = (s + 2 >= 3) ? s - 1 : s + 2;
            ISSUE(sn, kn);
        }
        asm volatile("cp.async.commit_group;\n");

#pragma unroll
        for (int kf = 0; kf < 2; kf++) {
            uint32_t aF[2][4], bF[2][4];
#pragma unroll
            for (int mf = 0; mf < 2; mf++)
                ldsm_x4(aF[mf][0], aF[mf][1], aF[mf][2], aF[mf][3],
                        &As[s][wm + mf * 16 + aLdRow][kf * 16 + aLdCol]);
#pragma unroll
            for (int g = 0; g < 2; g++)
                ldsm_x4(bF[g][0], bF[g][1], bF[g][2], bF[g][3],
                        &Bs[s][wn + g * 16 + bLdRow][kf * 16 + bLdCol]);
#pragma unroll
            for (int mf = 0; mf < 2; mf++)
#pragma unroll
                for (int nf = 0; nf < 4; nf++)
                    mma16816(c[mf][nf], aF[mf],
                             bF[nf >> 1][(nf & 1) * 2], bF[nf >> 1][(nf & 1) * 2 + 1]);
        }
        s = (s == 2) ? 0 : s + 1;
    }
#undef ISSUE

    // scatter epilogue
#pragma unroll
    for (int mf = 0; mf < 2; mf++) {
#pragma unroll
        for (int nf = 0; nf < 4; nf++) {
            int r0 = wm + mf * 16 + (lane >> 2);
            int col = n0 + wn + nf * 8 + 2 * (lane & 3);
            if (r0 < rem)
                *(float2*)(out + (size_t)sPos[r0] * IN_F + col) =
                    make_float2(c[mf][nf][0], c[mf][nf][1]);
            if (r0 + 8 < rem)
                *(float2*)(out + (size_t)sPos[r0 + 8] * IN_F + col) =
                    make_float2(c[mf][nf][2], c[mf][nf][3]);
        }
    }
}

// ---------------------------------------------------------------------------
extern "C" void kernel_launch(void* const* d_in, const int* in_sizes, int n_in,
                              void* d_out, int out_size) {
    const int*   tokens   = (const int*)d_in[0];
    const float* head_emb = (const float*)d_in[1];
    const float* t0e      = (const float*)d_in[2];
    const float* t0w      = (const float*)d_in[3];
    const float* t1e      = (const float*)d_in[4];
    const float* t1w      = (const float*)d_in[5];
    float* out = (float*)d_out;
    int n = in_sizes[0];
    if (n > NTOK_MAX) n = NTOK_MAX;

    init_k<<<1, 1>>>();
    classify_k<<<(n + 255) / 256, 256>>>(tokens, n);
    head_copy_k<<<n, 128>>>(tokens, head_emb, out);

    // pack passes (16 floats/thread)
    pack_emb_k<512, CUT1, 0><<<(n + 7) / 8, 256>>>(t0e, tokens, g_A0);
    pack_emb_k<256, CUT2, 1><<<(n + 15) / 16, 256>>>(t1e, tokens, g_A1);
    pack_w_k<512><<<1024 / 8, 256>>>(t0w, g_B0);
    pack_w_k<256><<<1024 / 16, 256>>>(t1w, g_B1);

    // dense GEMMs
    dim3 grid((n + 63) / 64, IN_F / 128);
    tail_mma2_k<1536, 0><<<grid, 256>>>(g_A0, g_B0, out);
    tail_mma2_k<768, 1><<<grid, 256>>>(g_A1, g_B1, out);
}

// round 5
// speedup vs baseline: 58.4976x; 58.4976x over previous
#include <cuda_runtime.h>
#include <cuda_bf16.h>
#include <cstdint>

#define NTOK_MAX (8 * 4096)
#define IN_F 1024
#define CUT1 5000
#define CUT2 20000

__device__ int g_cnt[2];
__device__ int g_idx0[NTOK_MAX];
__device__ int g_idx1[NTOK_MAX];

// ---------------------------------------------------------------------------
__global__ void init_k() { g_cnt[0] = 0; g_cnt[1] = 0; }

__global__ void classify_k(const int* __restrict__ tokens, int n) {
    int i = blockIdx.x * blockDim.x + threadIdx.x;
    int t = (i < n) ? tokens[i] : -1;
    int c = (t >= CUT2) ? 1 : ((t >= CUT1) ? 0 : -1);
    int lane = threadIdx.x & 31;
#pragma unroll
    for (int cc = 0; cc < 2; ++cc) {
        unsigned m = __ballot_sync(0xffffffffu, c == cc);
        if (c == cc) {
            int leader = __ffs(m) - 1;
            int base = 0;
            if (lane == leader) base = atomicAdd(&g_cnt[cc], __popc(m));
            base = __shfl_sync(m, base, leader);
            int off = base + __popc(m & ((1u << lane) - 1u));
            if (cc == 0) g_idx0[off] = i;
            else         g_idx1[off] = i;
        }
    }
}

__global__ void head_copy_k(const int* __restrict__ tokens,
                            const float* __restrict__ head_emb,
                            float* __restrict__ out) {
    int p = blockIdx.x;
    int t = __ldg(&tokens[p]);
    if (t >= CUT1) return;
    const float4* src = (const float4*)(head_emb + (size_t)t * IN_F);
    float4* dst = (float4*)(out + (size_t)p * IN_F);
    dst[threadIdx.x]       = src[threadIdx.x];
    dst[threadIdx.x + 128] = src[threadIdx.x + 128];
}

// ---------------------------------------------------------------------------
// Split 2 floats into bf16 hi pair + bf16 residual pair (5 instructions).
__device__ __forceinline__ void hilo2(float f0, float f1,
                                      uint32_t& hi2, uint32_t& lo2) {
    uint32_t h;
    asm("cvt.rn.bf16x2.f32 %0, %1, %2;" : "=r"(h) : "f"(f1), "f"(f0));
    float r0 = f0 - __uint_as_float(h << 16);          // exact
    float r1 = f1 - __uint_as_float(h & 0xffff0000u);  // exact
    asm("cvt.rn.bf16x2.f32 %0, %1, %2;" : "=r"(lo2) : "f"(r1), "f"(r0));
    hi2 = h;
}

__device__ __forceinline__ void ldsm_x4(uint32_t& r0, uint32_t& r1,
                                        uint32_t& r2, uint32_t& r3,
                                        const void* smem_ptr) {
    uint32_t addr = (uint32_t)__cvta_generic_to_shared(smem_ptr);
    asm volatile("ldmatrix.sync.aligned.m8n8.x4.shared.b16 {%0,%1,%2,%3}, [%4];"
                 : "=r"(r0), "=r"(r1), "=r"(r2), "=r"(r3) : "r"(addr));
}

__device__ __forceinline__ void mma16816(float* c, const uint32_t* a,
                                         uint32_t b0, uint32_t b1) {
    asm volatile(
        "mma.sync.aligned.m16n8k16.row.col.f32.bf16.bf16.f32 "
        "{%0,%1,%2,%3}, {%4,%5,%6,%7}, {%8,%9}, {%0,%1,%2,%3};"
        : "+f"(c[0]), "+f"(c[1]), "+f"(c[2]), "+f"(c[3])
        : "r"(a[0]), "r"(a[1]), "r"(a[2]), "r"(a[3]), "r"(b0), "r"(b1));
}

// ---------------------------------------------------------------------------
// Fused gather + split-bf16 tensor GEMM, no global scratch.
// out[pos, n] = sum_k emb[tok-LOW, k] * w[n, k]
// Tile 64(M) x 128(N), TK=32 source floats per chunk.
// Per chunk: convert once into Ah/Al/Bh/Bl smem, then 3 split products:
//   AhBh + AlBh + AhBl  (~fp32 accuracy, error ~2^-17).
template <int K, int LOW, int C>
__global__ void __launch_bounds__(256, 2)
tail_fused_k(const float* __restrict__ emb,
             const float* __restrict__ w,
             const int* __restrict__ tokens,
             float* __restrict__ out) {
    constexpr int TM = 64, TN = 128, LD = 40;   // LD halves: 32 + 8 pad
    constexpr int NC = K / 32;
    __shared__ __align__(16) __nv_bfloat16 sAh[TM][LD];
    __shared__ __align__(16) __nv_bfloat16 sAl[TM][LD];
    __shared__ __align__(16) __nv_bfloat16 sBh[TN][LD];
    __shared__ __align__(16) __nv_bfloat16 sBl[TN][LD];
    __shared__ int sPos[TM];

    const int count = g_cnt[C];
    const int rowBase = blockIdx.x * TM;
    if (rowBase >= count) return;
    const int rem = min(TM, count - rowBase);
    const int n0 = blockIdx.y * TN;
    const int tid = threadIdx.x;
    const int lane = tid & 31;
    const int wid = tid >> 5;
    const int* idxList = (C == 0) ? g_idx0 : g_idx1;

    if (tid < TM) sPos[tid] = idxList[rowBase + min(tid, rem - 1)];
    __syncthreads();

    // A loader: 64 rows x 4 threads x 8 floats
    const int ar = tid >> 2;
    const int aseg = (tid & 3) * 8;
    const float* aPtr = emb + (size_t)(__ldg(&tokens[sPos[ar]]) - LOW) * K + aseg;
    // B loader: 128 rows x 2 threads x 16 floats
    const int br = tid >> 1;
    const int bseg = (tid & 1) * 16;
    const float* bPtr = w + (size_t)(n0 + br) * K + bseg;

    float ra[8], rb[16];
    // prologue: chunk 0
    {
        float4 a0 = *(const float4*)(aPtr);
        float4 a1 = *(const float4*)(aPtr + 4);
        ra[0]=a0.x; ra[1]=a0.y; ra[2]=a0.z; ra[3]=a0.w;
        ra[4]=a1.x; ra[5]=a1.y; ra[6]=a1.z; ra[7]=a1.w;
#pragma unroll
        for (int q = 0; q < 4; q++) {
            float4 b = *(const float4*)(bPtr + q * 4);
            rb[q*4+0]=b.x; rb[q*4+1]=b.y; rb[q*4+2]=b.z; rb[q*4+3]=b.w;
        }
    }

    const int wm = (wid & 1) * 32;
    const int wn = (wid >> 1) * 32;
    float c[2][4][4];
#pragma unroll
    for (int i = 0; i < 2; i++)
#pragma unroll
        for (int j = 0; j < 4; j++)
#pragma unroll
            for (int q = 0; q < 4; q++) c[i][j][q] = 0.f;

    const int aLdRow = lane & 15;
    const int aLdCol = (lane >> 4) * 8;
    const int bLdRow = ((lane >> 4) << 3) + (lane & 7);
    const int bLdCol = lane & 8;

    for (int kc = 0; kc < NC; kc++) {
        __syncthreads();  // previous MMA done reading smem
        // convert + store chunk kc
        {
            uint32_t h0, h1, h2, h3, l0, l1, l2, l3;
            hilo2(ra[0], ra[1], h0, l0);
            hilo2(ra[2], ra[3], h1, l1);
            hilo2(ra[4], ra[5], h2, l2);
            hilo2(ra[6], ra[7], h3, l3);
            *(uint4*)&sAh[ar][aseg] = make_uint4(h0, h1, h2, h3);
            *(uint4*)&sAl[ar][aseg] = make_uint4(l0, l1, l2, l3);
#pragma unroll
            for (int q = 0; q < 2; q++) {
                uint32_t g0, g1, g2, g3, m0, m1, m2, m3;
                hilo2(rb[q*8+0], rb[q*8+1], g0, m0);
                hilo2(rb[q*8+2], rb[q*8+3], g1, m1);
                hilo2(rb[q*8+4], rb[q*8+5], g2, m2);
                hilo2(rb[q*8+6], rb[q*8+7], g3, m3);
                *(uint4*)&sBh[br][bseg + q*8] = make_uint4(g0, g1, g2, g3);
                *(uint4*)&sBl[br][bseg + q*8] = make_uint4(m0, m1, m2, m3);
            }
        }
        __syncthreads();

        // prefetch chunk kc+1 into regs (latency hides under MMA)
        if (kc + 1 < NC) {
            const float* ap = aPtr + (kc + 1) * 32;
            float4 a0 = *(const float4*)(ap);
            float4 a1 = *(const float4*)(ap + 4);
            ra[0]=a0.x; ra[1]=a0.y; ra[2]=a0.z; ra[3]=a0.w;
            ra[4]=a1.x; ra[5]=a1.y; ra[6]=a1.z; ra[7]=a1.w;
            const float* bp = bPtr + (kc + 1) * 32;
#pragma unroll
            for (int q = 0; q < 4; q++) {
                float4 b = *(const float4*)(bp + q * 4);
                rb[q*4+0]=b.x; rb[q*4+1]=b.y; rb[q*4+2]=b.z; rb[q*4+3]=b.w;
            }
        }

        // MMA: 2 k-fragments x 3 regions
#pragma unroll
        for (int kf = 0; kf < 2; kf++) {
            uint32_t AhF[2][4], AlF[2][4], BhF[2][4], BlF[2][4];
#pragma unroll
            for (int mf = 0; mf < 2; mf++) {
                ldsm_x4(AhF[mf][0], AhF[mf][1], AhF[mf][2], AhF[mf][3],
                        &sAh[wm + mf * 16 + aLdRow][kf * 16 + aLdCol]);
                ldsm_x4(AlF[mf][0], AlF[mf][1], AlF[mf][2], AlF[mf][3],
                        &sAl[wm + mf * 16 + aLdRow][kf * 16 + aLdCol]);
            }
#pragma unroll
            for (int g = 0; g < 2; g++) {
                ldsm_x4(BhF[g][0], BhF[g][1], BhF[g][2], BhF[g][3],
                        &sBh[wn + g * 16 + bLdRow][kf * 16 + bLdCol]);
                ldsm_x4(BlF[g][0], BlF[g][1], BlF[g][2], BlF[g][3],
                        &sBl[wn + g * 16 + bLdRow][kf * 16 + bLdCol]);
            }
#pragma unroll
            for (int mf = 0; mf < 2; mf++)
#pragma unroll
                for (int nf = 0; nf < 4; nf++) {
                    uint32_t bh0 = BhF[nf >> 1][(nf & 1) * 2];
                    uint32_t bh1 = BhF[nf >> 1][(nf & 1) * 2 + 1];
                    mma16816(c[mf][nf], AhF[mf], bh0, bh1);
                    mma16816(c[mf][nf], AlF[mf], bh0, bh1);
                    mma16816(c[mf][nf], AhF[mf],
                             BlF[nf >> 1][(nf & 1) * 2],
                             BlF[nf >> 1][(nf & 1) * 2 + 1]);
                }
        }
    }

    // scatter epilogue
#pragma unroll
    for (int mf = 0; mf < 2; mf++) {
#pragma unroll
        for (int nf = 0; nf < 4; nf++) {
            int r0 = wm + mf * 16 + (lane >> 2);
            int col = n0 + wn + nf * 8 + 2 * (lane & 3);
            if (r0 < rem)
                *(float2*)(out + (size_t)sPos[r0] * IN_F + col) =
                    make_float2(c[mf][nf][0], c[mf][nf][1]);
            if (r0 + 8 < rem)
                *(float2*)(out + (size_t)sPos[r0 + 8] * IN_F + col) =
                    make_float2(c[mf][nf][2], c[mf][nf][3]);
        }
    }
}

// ---------------------------------------------------------------------------
extern "C" void kernel_launch(void* const* d_in, const int* in_sizes, int n_in,
                              void* d_out, int out_size) {
    const int*   tokens   = (const int*)d_in[0];
    const float* head_emb = (const float*)d_in[1];
    const float* t0e      = (const float*)d_in[2];
    const float* t0w      = (const float*)d_in[3];
    const float* t1e      = (const float*)d_in[4];
    const float* t1w      = (const float*)d_in[5];
    float* out = (float*)d_out;
    int n = in_sizes[0];
    if (n > NTOK_MAX) n = NTOK_MAX;

    init_k<<<1, 1>>>();
    classify_k<<<(n + 255) / 256, 256>>>(tokens, n);
    head_copy_k<<<n, 128>>>(tokens, head_emb, out);

    dim3 grid((n + 63) / 64, IN_F / 128);
    tail_fused_k<512, CUT1, 0><<<grid, 256>>>(t0e, t0w, tokens, out);
    tail_fused_k<256, CUT2, 1><<<grid, 256>>>(t1e, t1w, tokens, out);
}